// round 12
// baseline (speedup 1.0000x reference)
#include <cuda_runtime.h>
#include <cuda_fp16.h>
#include <cstdint>

// ============================ problem constants ============================
constexpr int E = 512, H = 8, S = 64, TM = 64;

// ============================ device scratch (weights only) ================
// per head: {q_hi, k_hi, v_hi} 64x64 fp16 [s][t] SW128 tiles (8KB each) = 24KB/head
__device__ __align__(1024) unsigned char g_wqkv[H * 3 * 8192];
// Wu_hi chunks: bidx = nh*8 + kc -> [64k x 256n] fp16 swz512, 32KB each (512KB total)
__device__ __align__(1024) unsigned char g_wub[16 * 32768];

// ============================ helpers ======================================
__device__ __forceinline__ uint32_t smem_u32(const void* p) {
    uint32_t a;
    asm("{ .reg .u64 t; cvta.to.shared.u64 t, %1; cvt.u32.u64 %0, t; }" : "=r"(a) : "l"(p));
    return a;
}
__host__ __device__ __forceinline__ uint32_t swz128(uint32_t o) { return o ^ ((o >> 3) & 0x70); }
__host__ __device__ __forceinline__ uint32_t swz512(uint32_t o) { return o ^ ((o >> 5) & 0x70); }

__device__ __forceinline__ void ldsm_x4(uint32_t (&r)[4], uint32_t a) {
    asm volatile("ldmatrix.sync.aligned.m8n8.x4.shared.b16 {%0,%1,%2,%3}, [%4];"
        : "=r"(r[0]), "=r"(r[1]), "=r"(r[2]), "=r"(r[3]) : "r"(a));
}
__device__ __forceinline__ void ldsm_x4t(uint32_t (&r)[4], uint32_t a) {
    asm volatile("ldmatrix.sync.aligned.m8n8.x4.trans.shared.b16 {%0,%1,%2,%3}, [%4];"
        : "=r"(r[0]), "=r"(r[1]), "=r"(r[2]), "=r"(r[3]) : "r"(a));
}
__device__ __forceinline__ void mma16816(float (&d)[4], const uint32_t (&a)[4],
                                         uint32_t b0, uint32_t b1) {
    asm volatile("mma.sync.aligned.m16n8k16.row.col.f32.f16.f16.f32 "
        "{%0,%1,%2,%3}, {%4,%5,%6,%7}, {%8,%9}, {%0,%1,%2,%3};"
        : "+f"(d[0]), "+f"(d[1]), "+f"(d[2]), "+f"(d[3])
        : "r"(a[0]), "r"(a[1]), "r"(a[2]), "r"(a[3]), "r"(b0), "r"(b1));
}
__device__ __forceinline__ void cp16(uint32_t dst, const void* src) {
    asm volatile("cp.async.cg.shared.global [%0], [%1], 16;" :: "r"(dst), "l"(src));
}
#define CP_COMMIT() asm volatile("cp.async.commit_group;" ::: "memory")
#define CP_WAIT(n)  asm volatile("cp.async.wait_group %0;" :: "n"(n) : "memory")

__device__ __forceinline__ uint32_t pack2h(__half a, __half b) {
    __half2 p(a, b);
    return *reinterpret_cast<uint32_t*>(&p);
}
__device__ __forceinline__ uint32_t packf2(float2 v) {
    return pack2h(__float2half(v.x), __float2half(v.y));
}

// ============================ prep kernels =================================
// mats: 0=q_hi, 1=k_hi, 2=v_hi ; tile layout [s-rows][t-cols] fp16 SW128
__global__ void prep_qkv(const float* __restrict__ Wq, const float* __restrict__ Wk,
                         const float* __restrict__ Wv) {
    int idx = blockIdx.x * 256 + threadIdx.x;
    if (idx >= H * 3 * S * S) return;
    int h = idx / (3 * S * S);
    int mat = (idx >> 12) % 3;
    int s = (idx >> 6) & 63, t = idx & 63;
    const float* W = (mat == 0) ? Wq : ((mat == 1) ? Wk : Wv);
    float v = W[(h * S + s) * S + t];
    uint32_t off = swz128((uint32_t)(s * 128 + t * 2));
    *reinterpret_cast<__half*>(g_wqkv + (size_t)(h * 3 + mat) * 8192 + off) = __float2half(v);
}
// Wu_hi: chunk bidx = (n>>8)*8 + (k>>6): [64k x 256n] fp16 swz512
__global__ void prep_wu(const float* __restrict__ Wu) {
    int idx = blockIdx.x * 256 + threadIdx.x;
    if (idx >= E * E) return;
    int k = idx >> 9, n = idx & 511;
    int kc = k >> 6, kk = k & 63, nh = n >> 8, nn = n & 255;
    size_t base = (size_t)(nh * 8 + kc) * 32768;
    uint32_t off = swz512((uint32_t)(kk * 512 + nn * 2));
    *reinterpret_cast<__half*>(g_wub + base + off) = __float2half(Wu[idx]);
}

// ============================ fused kernel =================================
// smem map (bytes), 112KB total -> 2 CTAs/SM:
//   sT  @ 0     : 8 tiles [64r x 64k] fp16 SW128 (head h = k-chunk h) = 64KB
//   BUF @ 65536 : phase1 = W head-pair (48KB)
//                 phase2 = per-warp B rings: warp w @ BUF + w*6KB, 3 x 2KB bufs
constexpr uint32_t ST = 0, BUF = 65536;
constexpr uint32_t SMEM_TOTAL = 114688;

__global__ __launch_bounds__(256, 2)
void fused_sparse_attn(const float* __restrict__ x,
                       const float* __restrict__ bq, const float* __restrict__ bk,
                       const float* __restrict__ bv,
                       const float* __restrict__ bu, float* __restrict__ out)
{
    extern __shared__ unsigned char smem[];
    const uint32_t sb = smem_u32(smem);
    const int tid = threadIdx.x, lane = tid & 31, wid = tid >> 5;
    const int row0 = blockIdx.x * TM;
    const float SC = 0.04419417382415922f;   // 1/sqrt(512)

    const int g  = lane >> 2;
    const int qd = lane & 3;
    const uint32_t hiSel = (uint32_t)((lane >> 4) << 4);

    // ===================== Phase 1: QKV + softmax -> sT ====================
    const int lh = wid >> 2;                  // local head in pair
    const int wm = wid & 3;                   // 16-row m position

    for (int hp = 0; hp < 4; ++hp) {
        // -- stage W head-pair (pre-swizzled, 48KB contiguous) --
        {
            const char* src = (const char*)g_wqkv + (size_t)hp * 49152;
            #pragma unroll
            for (int i = 0; i < 12; ++i) {
                uint32_t o = (uint32_t)(tid + i * 256) * 16;
                cp16(sb + BUF + o, src + o);
            }
            CP_COMMIT();
        }
        // -- A fragments straight from gmem (overlaps the cp.async W load) --
        uint32_t aF[4][4];
        {
            const float* xr0 = x + (size_t)(row0 + wm * 16 + g) * E + hp * 128 + lh * 64;
            const float* xr1 = xr0 + 8 * (size_t)E;
            #pragma unroll
            for (int ks = 0; ks < 4; ++ks) {
                int c = ks * 16 + qd * 2;
                aF[ks][0] = packf2(*reinterpret_cast<const float2*>(xr0 + c));
                aF[ks][1] = packf2(*reinterpret_cast<const float2*>(xr1 + c));
                aF[ks][2] = packf2(*reinterpret_cast<const float2*>(xr0 + c + 8));
                aF[ks][3] = packf2(*reinterpret_cast<const float2*>(xr1 + c + 8));
            }
        }
        CP_WAIT(0);
        __syncthreads();          // W(hp) visible to all warps

        const int h = hp * 2 + lh;
        const uint32_t wbase = sb + BUF + (uint32_t)lh * 24576;

        float aq[8][4], ak[8][4];
        #pragma unroll
        for (int nt = 0; nt < 8; ++nt)
            #pragma unroll
            for (int c = 0; c < 4; ++c) { aq[nt][c] = 0.f; ak[nt][c] = 0.f; }

        // pass A: q and k
        #pragma unroll
        for (int ks = 0; ks < 4; ++ks) {
            #pragma unroll
            for (int ntp = 0; ntp < 4; ++ntp) {
                uint32_t boff = swz128((uint32_t)(ks * 16 + (lane & 15)) * 128
                                       + (uint32_t)ntp * 32 + hiSel);
                uint32_t bQ[4], bK[4];
                ldsm_x4t(bQ, wbase + boff);
                ldsm_x4t(bK, wbase + 8192 + boff);
                mma16816(aq[2*ntp],   aF[ks], bQ[0], bQ[1]);
                mma16816(aq[2*ntp+1], aF[ks], bQ[2], bQ[3]);
                mma16816(ak[2*ntp],   aF[ks], bK[0], bK[1]);
                mma16816(ak[2*ntp+1], aF[ks], bK[2], bK[3]);
            }
        }
        // pass B: v
        float av[8][4];
        #pragma unroll
        for (int nt = 0; nt < 8; ++nt)
            #pragma unroll
            for (int c = 0; c < 4; ++c) av[nt][c] = 0.f;
        #pragma unroll
        for (int ks = 0; ks < 4; ++ks) {
            #pragma unroll
            for (int ntp = 0; ntp < 4; ++ntp) {
                uint32_t boff = swz128((uint32_t)(ks * 16 + (lane & 15)) * 128
                                       + (uint32_t)ntp * 32 + hiSel);
                uint32_t bV[4];
                ldsm_x4t(bV, wbase + 16384 + boff);
                mma16816(av[2*ntp],   aF[ks], bV[0], bV[1]);
                mma16816(av[2*ntp+1], aF[ks], bV[2], bV[3]);
            }
        }

        // -- softmax (quad-local), reuse aq<-e, av<-v+bias --
        const float* bqh = bq + h * S;
        const float* bkh = bk + h * S;
        const float* bvh = bv + h * S;
        float ssum0 = 0.f, ssum1 = 0.f;
        #pragma unroll
        for (int nt = 0; nt < 8; ++nt) {
            int col0 = nt * 8 + qd * 2;
            float2 b1 = *reinterpret_cast<const float2*>(bqh + col0);
            float2 b2 = *reinterpret_cast<const float2*>(bkh + col0);
            float2 b3 = *reinterpret_cast<const float2*>(bvh + col0);
            float e;
            e = __expf((aq[nt][0] + b1.x) * (ak[nt][0] + b2.x) * SC); aq[nt][0] = e; ssum0 += e;
            e = __expf((aq[nt][1] + b1.y) * (ak[nt][1] + b2.y) * SC); aq[nt][1] = e; ssum0 += e;
            e = __expf((aq[nt][2] + b1.x) * (ak[nt][2] + b2.x) * SC); aq[nt][2] = e; ssum1 += e;
            e = __expf((aq[nt][3] + b1.y) * (ak[nt][3] + b2.y) * SC); aq[nt][3] = e; ssum1 += e;
            av[nt][0] += b3.x; av[nt][1] += b3.y;
            av[nt][2] += b3.x; av[nt][3] += b3.y;
        }
        ssum0 += __shfl_xor_sync(0xffffffffu, ssum0, 1);
        ssum0 += __shfl_xor_sync(0xffffffffu, ssum0, 2);
        ssum1 += __shfl_xor_sync(0xffffffffu, ssum1, 1);
        ssum1 += __shfl_xor_sync(0xffffffffu, ssum1, 2);
        const float inv0 = 1.0f / ssum0, inv1 = 1.0f / ssum1;

        {
            int rt0 = wm * 16 + g;
            #pragma unroll
            for (int nt = 0; nt < 8; ++nt) {
                uint32_t cb = (uint32_t)((nt * 8 + qd * 2) * 2);
                uint32_t offBase = (uint32_t)h * 8192;
                float t0 = aq[nt][0] * inv0 * av[nt][0];
                float t1 = aq[nt][1] * inv0 * av[nt][1];
                float t2 = aq[nt][2] * inv1 * av[nt][2];
                float t3 = aq[nt][3] * inv1 * av[nt][3];
                *reinterpret_cast<uint32_t*>(smem + ST + offBase
                    + swz128((uint32_t)rt0 * 128 + cb)) =
                    pack2h(__float2half(t0), __float2half(t1));
                *reinterpret_cast<uint32_t*>(smem + ST + offBase
                    + swz128((uint32_t)(rt0 + 8) * 128 + cb)) =
                    pack2h(__float2half(t2), __float2half(t3));
            }
        }
        __syncthreads();   // BUF (W) safe to overwrite; sT coherent after last hp
    }
    // After the final barrier above, sT is coherent and BUF is free.
    // Phase 2 is BARRIER-FREE: B slices are warp-private.

    // ===================== Phase 2: out = t @ Wu_hi + bu ===================
    // warp = 64 rows x 32 cols (pn = wid); per-warp B ring: 3 x 2KB @ wbuf.
    // Per-warp buffer layout: row r (0..31) at r*64, 16B block j stored at
    // column quad (j ^ ((r>>1)&3)) -> ldmatrix 8-row reads are conflict-free.
    const int pn = wid;
    const uint32_t wbuf = sb + BUF + (uint32_t)wid * 6144;

    auto load_sub_w = [&](int s, int buf) {
        int nh = s >> 4, kc = (s >> 1) & 7, half = s & 1;
        const char* src = (const char*)g_wub + (size_t)(nh * 8 + kc) * 32768;
        uint32_t rowOff = (uint32_t)(half * 32 + lane) * 512 + (uint32_t)pn * 64;
        uint32_t d = wbuf + (uint32_t)buf * 2048 + (uint32_t)lane * 64;
        #pragma unroll
        for (int j = 0; j < 4; ++j) {
            uint32_t so = rowOff + (uint32_t)j * 16;
            so ^= (so >> 5) & 0x70;                        // swz512
            uint32_t doff = (uint32_t)((j ^ ((lane >> 1) & 3)) << 4);
            cp16(d + doff, src + so);
        }
        CP_COMMIT();
    };

    load_sub_w(0, 0);
    load_sub_w(1, 1);

    #pragma unroll
    for (int nh = 0; nh < 2; ++nh) {
        float acc[16][4];   // [mf*4 + nf]
        #pragma unroll
        for (int nf = 0; nf < 16; ++nf)
            #pragma unroll
            for (int c = 0; c < 4; ++c) acc[nf][c] = 0.f;

        #pragma unroll
        for (int s16 = 0; s16 < 16; ++s16) {
            const int s = nh * 16 + s16;
            if (s + 2 < 32) { load_sub_w(s + 2, (s + 2) % 3); CP_WAIT(2); }
            else if (s + 2 == 32) { CP_WAIT(1); }
            else { CP_WAIT(0); }

            const int kc = s16 >> 1, half = s16 & 1;
            const uint32_t bb = wbuf + (uint32_t)(s % 3) * 2048;
            const uint32_t tA = sb + ST + (uint32_t)kc * 8192;
            #pragma unroll
            for (int ksg = 0; ksg < 2; ++ksg) {
                uint32_t kOff = (uint32_t)(half * 64 + ksg * 32) + hiSel;
                uint32_t a[4][4];
                #pragma unroll
                for (int mf = 0; mf < 4; ++mf)
                    ldsm_x4(a[mf], tA + swz128((uint32_t)(mf * 16 + (lane & 15)) * 128 + kOff));
                #pragma unroll
                for (int ntp = 0; ntp < 2; ++ntp) {
                    uint32_t r = (uint32_t)(ksg * 16) + (lane & 15);
                    uint32_t cb = (uint32_t)ntp * 32 + hiSel;
                    uint32_t baddr = bb + r * 64
                                   + ((((cb >> 4) ^ ((r >> 1) & 3))) << 4);
                    uint32_t b[4];
                    ldsm_x4t(b, baddr);
                    #pragma unroll
                    for (int mf = 0; mf < 4; ++mf) {
                        mma16816(acc[mf * 4 + ntp * 2],     a[mf], b[0], b[1]);
                        mma16816(acc[mf * 4 + ntp * 2 + 1], a[mf], b[2], b[3]);
                    }
                }
            }
        }

        // epilogue for this N-half
        #pragma unroll
        for (int mf = 0; mf < 4; ++mf) {
            int r0 = row0 + mf * 16 + g;
            #pragma unroll
            for (int nf = 0; nf < 4; ++nf) {
                int col0 = nh * 256 + pn * 32 + nf * 8 + qd * 2;
                float2 bb2 = *reinterpret_cast<const float2*>(bu + col0);
                const float* a = acc[mf * 4 + nf];
                float2 o0 = make_float2(a[0] + bb2.x, a[1] + bb2.y);
                float2 o1 = make_float2(a[2] + bb2.x, a[3] + bb2.y);
                *reinterpret_cast<float2*>(out + (size_t)r0 * E + col0)       = o0;
                *reinterpret_cast<float2*>(out + (size_t)(r0 + 8) * E + col0) = o1;
            }
        }
    }
}

// ============================ launch =======================================
extern "C" void kernel_launch(void* const* d_in, const int* in_sizes, int n_in,
                              void* d_out, int out_size)
{
    const float* x  = (const float*)d_in[0];
    const float* Wq = (const float*)d_in[1];
    const float* bq = (const float*)d_in[2];
    const float* Wk = (const float*)d_in[3];
    const float* bk = (const float*)d_in[4];
    const float* Wv = (const float*)d_in[5];
    const float* bv = (const float*)d_in[6];
    const float* Wu = (const float*)d_in[7];
    const float* bu = (const float*)d_in[8];
    float* out = (float*)d_out;

    const int Nrows = in_sizes[0] / E;
    const int tiles = Nrows / TM;   // 2048

    cudaFuncSetAttribute(fused_sparse_attn,
                         cudaFuncAttributeMaxDynamicSharedMemorySize, SMEM_TOTAL);

    prep_qkv<<<(H * 3 * S * S + 255) / 256, 256>>>(Wq, Wk, Wv);
    prep_wu<<<(E * E + 255) / 256, 256>>>(Wu);
    fused_sparse_attn<<<tiles, 256, SMEM_TOTAL>>>(x, bq, bk, bv, bu, out);
}

// round 13
// speedup vs baseline: 1.1279x; 1.1279x over previous
#include <cuda_runtime.h>
#include <cuda_fp16.h>
#include <cstdint>

// ============================ problem constants ============================
constexpr int E = 512, H = 8, S = 64, TM = 64;

// ============================ device scratch (weights only) ================
// per head: {q_hi, k_hi, v_hi} 64x64 fp16 [s][t] SW128 tiles (8KB each) = 24KB/head
__device__ __align__(1024) unsigned char g_wqkv[H * 3 * 8192];
// Wu_hi chunks: bidx = nh*8 + kc -> [64k x 256n] fp16 swz512, 32KB each (512KB total)
__device__ __align__(1024) unsigned char g_wub[16 * 32768];

// ============================ helpers ======================================
__device__ __forceinline__ uint32_t smem_u32(const void* p) {
    uint32_t a;
    asm("{ .reg .u64 t; cvta.to.shared.u64 t, %1; cvt.u32.u64 %0, t; }" : "=r"(a) : "l"(p));
    return a;
}
__host__ __device__ __forceinline__ uint32_t swz128(uint32_t o) { return o ^ ((o >> 3) & 0x70); }
__host__ __device__ __forceinline__ uint32_t swz512(uint32_t o) { return o ^ ((o >> 5) & 0x70); }

__device__ __forceinline__ void ldsm_x4(uint32_t (&r)[4], uint32_t a) {
    asm volatile("ldmatrix.sync.aligned.m8n8.x4.shared.b16 {%0,%1,%2,%3}, [%4];"
        : "=r"(r[0]), "=r"(r[1]), "=r"(r[2]), "=r"(r[3]) : "r"(a));
}
__device__ __forceinline__ void ldsm_x4t(uint32_t (&r)[4], uint32_t a) {
    asm volatile("ldmatrix.sync.aligned.m8n8.x4.trans.shared.b16 {%0,%1,%2,%3}, [%4];"
        : "=r"(r[0]), "=r"(r[1]), "=r"(r[2]), "=r"(r[3]) : "r"(a));
}
__device__ __forceinline__ void mma16816(float (&d)[4], const uint32_t (&a)[4],
                                         uint32_t b0, uint32_t b1) {
    asm volatile("mma.sync.aligned.m16n8k16.row.col.f32.f16.f16.f32 "
        "{%0,%1,%2,%3}, {%4,%5,%6,%7}, {%8,%9}, {%0,%1,%2,%3};"
        : "+f"(d[0]), "+f"(d[1]), "+f"(d[2]), "+f"(d[3])
        : "r"(a[0]), "r"(a[1]), "r"(a[2]), "r"(a[3]), "r"(b0), "r"(b1));
}
__device__ __forceinline__ void cp16(uint32_t dst, const void* src) {
    asm volatile("cp.async.cg.shared.global [%0], [%1], 16;" :: "r"(dst), "l"(src));
}
#define CP_COMMIT() asm volatile("cp.async.commit_group;" ::: "memory")
#define CP_WAIT(n)  asm volatile("cp.async.wait_group %0;" :: "n"(n) : "memory")

__device__ __forceinline__ uint32_t pack2h(__half a, __half b) {
    __half2 p(a, b);
    return *reinterpret_cast<uint32_t*>(&p);
}
__device__ __forceinline__ uint32_t packf2(float2 v) {
    return pack2h(__float2half(v.x), __float2half(v.y));
}

// ============================ prep kernels =================================
// mats: 0=q_hi, 1=k_hi, 2=v_hi ; tile layout [s-rows][t-cols] fp16 SW128
__global__ void prep_qkv(const float* __restrict__ Wq, const float* __restrict__ Wk,
                         const float* __restrict__ Wv) {
    int idx = blockIdx.x * 256 + threadIdx.x;
    if (idx >= H * 3 * S * S) return;
    int h = idx / (3 * S * S);
    int mat = (idx >> 12) % 3;
    int s = (idx >> 6) & 63, t = idx & 63;
    const float* W = (mat == 0) ? Wq : ((mat == 1) ? Wk : Wv);
    float v = W[(h * S + s) * S + t];
    uint32_t off = swz128((uint32_t)(s * 128 + t * 2));
    *reinterpret_cast<__half*>(g_wqkv + (size_t)(h * 3 + mat) * 8192 + off) = __float2half(v);
}
// Wu_hi: chunk bidx = (n>>8)*8 + (k>>6): [64k x 256n] fp16 swz512
__global__ void prep_wu(const float* __restrict__ Wu) {
    int idx = blockIdx.x * 256 + threadIdx.x;
    if (idx >= E * E) return;
    int k = idx >> 9, n = idx & 511;
    int kc = k >> 6, kk = k & 63, nh = n >> 8, nn = n & 255;
    size_t base = (size_t)(nh * 8 + kc) * 32768;
    uint32_t off = swz512((uint32_t)(kk * 512 + nn * 2));
    *reinterpret_cast<__half*>(g_wub + base + off) = __float2half(Wu[idx]);
}

// ============================ fused kernel =================================
// smem map (bytes), 112KB total -> 2 CTAs/SM:
//   sT  @ 0     : 8 tiles [64r x 64k] fp16 SW128 (head h = k-chunk h) = 64KB
//   BUF @ 65536 : phase1 = W head-pair (48KB); phase2 = B 2 x 16KB sub-chunks
constexpr uint32_t ST = 0, BUF = 65536;
constexpr uint32_t SMEM_TOTAL = 114688;

__global__ __launch_bounds__(256, 2)
void fused_sparse_attn(const float* __restrict__ x,
                       const float* __restrict__ bq, const float* __restrict__ bk,
                       const float* __restrict__ bv,
                       const float* __restrict__ bu, float* __restrict__ out)
{
    extern __shared__ unsigned char smem[];
    const uint32_t sb = smem_u32(smem);
    const int tid = threadIdx.x, lane = tid & 31, wid = tid >> 5;
    const int row0 = blockIdx.x * TM;
    const float SC = 0.04419417382415922f;   // 1/sqrt(512)

    const int g  = lane >> 2;
    const int qd = lane & 3;
    const uint32_t hiSel = (uint32_t)((lane >> 4) << 4);

    // ===================== Phase 1: QKV + softmax -> sT ====================
    const int lh = wid >> 2;                  // local head in pair
    const int wm = wid & 3;                   // 16-row m position

    auto load_W = [&](int hp) {
        const char* src = (const char*)g_wqkv + (size_t)hp * 49152;
        #pragma unroll
        for (int i = 0; i < 12; ++i) {
            uint32_t o = (uint32_t)(tid + i * 256) * 16;
            cp16(sb + BUF + o, src + o);
        }
        CP_COMMIT();
    };

    load_W(0);

    for (int hp = 0; hp < 4; ++hp) {
        // -- A fragments straight from gmem (overlap the in-flight W load) --
        uint32_t aF[4][4];
        {
            const float* xr0 = x + (size_t)(row0 + wm * 16 + g) * E + hp * 128 + lh * 64;
            const float* xr1 = xr0 + 8 * (size_t)E;
            #pragma unroll
            for (int ks = 0; ks < 4; ++ks) {
                int c = ks * 16 + qd * 2;
                aF[ks][0] = packf2(*reinterpret_cast<const float2*>(xr0 + c));
                aF[ks][1] = packf2(*reinterpret_cast<const float2*>(xr1 + c));
                aF[ks][2] = packf2(*reinterpret_cast<const float2*>(xr0 + c + 8));
                aF[ks][3] = packf2(*reinterpret_cast<const float2*>(xr1 + c + 8));
            }
        }
        CP_WAIT(0);
        __syncthreads();          // W(hp) visible to all warps

        const int h = hp * 2 + lh;
        const uint32_t wbase = sb + BUF + (uint32_t)lh * 24576;

        float aq[8][4], ak[8][4];
        #pragma unroll
        for (int nt = 0; nt < 8; ++nt)
            #pragma unroll
            for (int c = 0; c < 4; ++c) { aq[nt][c] = 0.f; ak[nt][c] = 0.f; }

        // pass A: q and k
        #pragma unroll
        for (int ks = 0; ks < 4; ++ks) {
            #pragma unroll
            for (int ntp = 0; ntp < 4; ++ntp) {
                uint32_t boff = swz128((uint32_t)(ks * 16 + (lane & 15)) * 128
                                       + (uint32_t)ntp * 32 + hiSel);
                uint32_t bQ[4], bK[4];
                ldsm_x4t(bQ, wbase + boff);
                ldsm_x4t(bK, wbase + 8192 + boff);
                mma16816(aq[2*ntp],   aF[ks], bQ[0], bQ[1]);
                mma16816(aq[2*ntp+1], aF[ks], bQ[2], bQ[3]);
                mma16816(ak[2*ntp],   aF[ks], bK[0], bK[1]);
                mma16816(ak[2*ntp+1], aF[ks], bK[2], bK[3]);
            }
        }
        // pass B: v
        float av[8][4];
        #pragma unroll
        for (int nt = 0; nt < 8; ++nt)
            #pragma unroll
            for (int c = 0; c < 4; ++c) av[nt][c] = 0.f;
        #pragma unroll
        for (int ks = 0; ks < 4; ++ks) {
            #pragma unroll
            for (int ntp = 0; ntp < 4; ++ntp) {
                uint32_t boff = swz128((uint32_t)(ks * 16 + (lane & 15)) * 128
                                       + (uint32_t)ntp * 32 + hiSel);
                uint32_t bV[4];
                ldsm_x4t(bV, wbase + 16384 + boff);
                mma16816(av[2*ntp],   aF[ks], bV[0], bV[1]);
                mma16816(av[2*ntp+1], aF[ks], bV[2], bV[3]);
            }
        }

        __syncthreads();              // all warps done READING W(hp)
        if (hp < 3) load_W(hp + 1);   // prefetch W(hp+1): overlaps softmax+stores

        // -- softmax (quad-local), reuse aq<-e, av<-v+bias --
        const float* bqh = bq + h * S;
        const float* bkh = bk + h * S;
        const float* bvh = bv + h * S;
        float ssum0 = 0.f, ssum1 = 0.f;
        #pragma unroll
        for (int nt = 0; nt < 8; ++nt) {
            int col0 = nt * 8 + qd * 2;
            float2 b1 = *reinterpret_cast<const float2*>(bqh + col0);
            float2 b2 = *reinterpret_cast<const float2*>(bkh + col0);
            float2 b3 = *reinterpret_cast<const float2*>(bvh + col0);
            float e;
            e = __expf((aq[nt][0] + b1.x) * (ak[nt][0] + b2.x) * SC); aq[nt][0] = e; ssum0 += e;
            e = __expf((aq[nt][1] + b1.y) * (ak[nt][1] + b2.y) * SC); aq[nt][1] = e; ssum0 += e;
            e = __expf((aq[nt][2] + b1.x) * (ak[nt][2] + b2.x) * SC); aq[nt][2] = e; ssum1 += e;
            e = __expf((aq[nt][3] + b1.y) * (ak[nt][3] + b2.y) * SC); aq[nt][3] = e; ssum1 += e;
            av[nt][0] += b3.x; av[nt][1] += b3.y;
            av[nt][2] += b3.x; av[nt][3] += b3.y;
        }
        ssum0 += __shfl_xor_sync(0xffffffffu, ssum0, 1);
        ssum0 += __shfl_xor_sync(0xffffffffu, ssum0, 2);
        ssum1 += __shfl_xor_sync(0xffffffffu, ssum1, 1);
        ssum1 += __shfl_xor_sync(0xffffffffu, ssum1, 2);
        const float inv0 = 1.0f / ssum0, inv1 = 1.0f / ssum1;

        {
            int rt0 = wm * 16 + g;
            #pragma unroll
            for (int nt = 0; nt < 8; ++nt) {
                uint32_t cb = (uint32_t)((nt * 8 + qd * 2) * 2);
                uint32_t offBase = (uint32_t)h * 8192;
                float t0 = aq[nt][0] * inv0 * av[nt][0];
                float t1 = aq[nt][1] * inv0 * av[nt][1];
                float t2 = aq[nt][2] * inv1 * av[nt][2];
                float t3 = aq[nt][3] * inv1 * av[nt][3];
                *reinterpret_cast<uint32_t*>(smem + ST + offBase
                    + swz128((uint32_t)rt0 * 128 + cb)) =
                    pack2h(__float2half(t0), __float2half(t1));
                *reinterpret_cast<uint32_t*>(smem + ST + offBase
                    + swz128((uint32_t)(rt0 + 8) * 128 + cb)) =
                    pack2h(__float2half(t2), __float2half(t3));
            }
        }
    }
    __syncthreads();   // sT coherent; BUF free for phase 2

    // ===================== Phase 2: out = t @ Wu_hi + bu ===================
    // warp = 64 rows x 32 cols (pn = wid): B read exactly once -> crossbar unbound
    const int pn = wid;

    // B sub-chunk: step s (0..31): nh=s>>4, kc=(s>>1)&7, half=s&1 -> 16KB contiguous
    auto load_sub = [&](int s, int buf) {
        int nh = s >> 4, kc = (s >> 1) & 7, half = s & 1;
        const char* src = (const char*)g_wub + (size_t)(nh * 8 + kc) * 32768
                        + (size_t)half * 16384;
        uint32_t d = sb + BUF + (uint32_t)buf * 16384;
        #pragma unroll
        for (int i = 0; i < 4; ++i) {
            uint32_t o = (uint32_t)(tid + i * 256) * 16;
            cp16(d + o, src + o);
        }
    };

    load_sub(0, 0);
    CP_COMMIT();

    for (int nh = 0; nh < 2; ++nh) {
        float acc[16][4];   // [mf*4 + nf][..] : 4 m16 frags x 4 n8 frags
        #pragma unroll
        for (int nf = 0; nf < 16; ++nf)
            #pragma unroll
            for (int c = 0; c < 4; ++c) acc[nf][c] = 0.f;

        for (int s16 = 0; s16 < 16; ++s16) {
            int s = nh * 16 + s16;
            CP_WAIT(0);
            __syncthreads();
            if (s + 1 < 32) { load_sub(s + 1, (s + 1) & 1); CP_COMMIT(); }

            int kc = s16 >> 1, half = s16 & 1;
            uint32_t bb = sb + BUF + (uint32_t)(s & 1) * 16384;
            uint32_t tA = sb + ST + (uint32_t)kc * 8192;
            #pragma unroll
            for (int ksg = 0; ksg < 2; ++ksg) {
                uint32_t kOff = (uint32_t)(half * 64 + ksg * 32) + hiSel;
                uint32_t a[4][4];
                #pragma unroll
                for (int mf = 0; mf < 4; ++mf)
                    ldsm_x4(a[mf], tA + swz128((uint32_t)(mf * 16 + (lane & 15)) * 128 + kOff));
                #pragma unroll
                for (int ntp = 0; ntp < 2; ++ntp) {
                    uint32_t boff = swz512((uint32_t)(ksg * 16 + (lane & 15)) * 512
                                           + (uint32_t)(pn * 64 + ntp * 32) + hiSel);
                    uint32_t b[4];
                    ldsm_x4t(b, bb + boff);
                    #pragma unroll
                    for (int mf = 0; mf < 4; ++mf) {
                        mma16816(acc[mf * 4 + ntp * 2],     a[mf], b[0], b[1]);
                        mma16816(acc[mf * 4 + ntp * 2 + 1], a[mf], b[2], b[3]);
                    }
                }
            }
        }

        // epilogue for this N-half
        #pragma unroll
        for (int mf = 0; mf < 4; ++mf) {
            int r0 = row0 + mf * 16 + g;
            #pragma unroll
            for (int nf = 0; nf < 4; ++nf) {
                int col0 = nh * 256 + pn * 32 + nf * 8 + qd * 2;
                float2 bb2 = *reinterpret_cast<const float2*>(bu + col0);
                const float* a = acc[mf * 4 + nf];
                float2 o0 = make_float2(a[0] + bb2.x, a[1] + bb2.y);
                float2 o1 = make_float2(a[2] + bb2.x, a[3] + bb2.y);
                *reinterpret_cast<float2*>(out + (size_t)r0 * E + col0)       = o0;
                *reinterpret_cast<float2*>(out + (size_t)(r0 + 8) * E + col0) = o1;
            }
        }
    }
}

// ============================ launch =======================================
extern "C" void kernel_launch(void* const* d_in, const int* in_sizes, int n_in,
                              void* d_out, int out_size)
{
    const float* x  = (const float*)d_in[0];
    const float* Wq = (const float*)d_in[1];
    const float* bq = (const float*)d_in[2];
    const float* Wk = (const float*)d_in[3];
    const float* bk = (const float*)d_in[4];
    const float* Wv = (const float*)d_in[5];
    const float* bv = (const float*)d_in[6];
    const float* Wu = (const float*)d_in[7];
    const float* bu = (const float*)d_in[8];
    float* out = (float*)d_out;

    const int Nrows = in_sizes[0] / E;
    const int tiles = Nrows / TM;   // 2048

    cudaFuncSetAttribute(fused_sparse_attn,
                         cudaFuncAttributeMaxDynamicSharedMemorySize, SMEM_TOTAL);

    prep_qkv<<<(H * 3 * S * S + 255) / 256, 256>>>(Wq, Wk, Wv);
    prep_wu<<<(E * E + 255) / 256, 256>>>(Wu);
    fused_sparse_attn<<<tiles, 256, SMEM_TOTAL>>>(x, bq, bk, bv, bu, out);
}

// round 15
// speedup vs baseline: 1.1605x; 1.0289x over previous
#include <cuda_runtime.h>
#include <cuda_fp16.h>
#include <cstdint>

// ============================ problem constants ============================
constexpr int E = 512, H = 8, S = 64, TM = 64;

// ============================ device scratch (weights only) ================
// per head: {q_hi, k_hi, v_hi} 64x64 fp16 [s][t] SW128 tiles (8KB each) = 24KB/head
__device__ __align__(1024) unsigned char g_wqkv[H * 3 * 8192];
// Wu_hi chunks: bidx = nh*8 + kc -> [64k x 256n] fp16 swz512, 32KB each (512KB total)
__device__ __align__(1024) unsigned char g_wub[16 * 32768];

// ============================ helpers ======================================
__device__ __forceinline__ uint32_t smem_u32(const void* p) {
    uint32_t a;
    asm("{ .reg .u64 t; cvta.to.shared.u64 t, %1; cvt.u32.u64 %0, t; }" : "=r"(a) : "l"(p));
    return a;
}
__host__ __device__ __forceinline__ uint32_t swz128(uint32_t o) { return o ^ ((o >> 3) & 0x70); }
__host__ __device__ __forceinline__ uint32_t swz512(uint32_t o) { return o ^ ((o >> 5) & 0x70); }

__device__ __forceinline__ void ldsm_x4(uint32_t (&r)[4], uint32_t a) {
    asm volatile("ldmatrix.sync.aligned.m8n8.x4.shared.b16 {%0,%1,%2,%3}, [%4];"
        : "=r"(r[0]), "=r"(r[1]), "=r"(r[2]), "=r"(r[3]) : "r"(a));
}
__device__ __forceinline__ void ldsm_x4t(uint32_t (&r)[4], uint32_t a) {
    asm volatile("ldmatrix.sync.aligned.m8n8.x4.trans.shared.b16 {%0,%1,%2,%3}, [%4];"
        : "=r"(r[0]), "=r"(r[1]), "=r"(r[2]), "=r"(r[3]) : "r"(a));
}
__device__ __forceinline__ void mma16816(float (&d)[4], const uint32_t (&a)[4],
                                         uint32_t b0, uint32_t b1) {
    asm volatile("mma.sync.aligned.m16n8k16.row.col.f32.f16.f16.f32 "
        "{%0,%1,%2,%3}, {%4,%5,%6,%7}, {%8,%9}, {%0,%1,%2,%3};"
        : "+f"(d[0]), "+f"(d[1]), "+f"(d[2]), "+f"(d[3])
        : "r"(a[0]), "r"(a[1]), "r"(a[2]), "r"(a[3]), "r"(b0), "r"(b1));
}
__device__ __forceinline__ void cp16(uint32_t dst, const void* src) {
    asm volatile("cp.async.cg.shared.global [%0], [%1], 16;" :: "r"(dst), "l"(src));
}
#define CP_COMMIT() asm volatile("cp.async.commit_group;" ::: "memory")
#define CP_WAIT(n)  asm volatile("cp.async.wait_group %0;" :: "n"(n) : "memory")

// -- mbarrier primitives --
#define MBAR_INIT(mb, c) \
    asm volatile("mbarrier.init.shared.b64 [%0], %1;" :: "r"(mb), "r"(c) : "memory")
__device__ __forceinline__ void mbar_arrive(uint32_t mb) {
    asm volatile("mbarrier.arrive.shared.b64 _, [%0];" :: "r"(mb) : "memory");
}
// arrive-on when this thread's prior cp.asyncs complete; .noinc = don't bump count
__device__ __forceinline__ void cp_mbar_arrive_noinc(uint32_t mb) {
    asm volatile("cp.async.mbarrier.arrive.noinc.shared.b64 [%0];" :: "r"(mb) : "memory");
}
__device__ __forceinline__ void mbar_wait(uint32_t mb, uint32_t parity) {
    asm volatile(
        "{\n\t.reg .pred P;\n\t"
        "W_%=:\n\t"
        "mbarrier.try_wait.parity.acquire.cta.shared::cta.b64 P, [%0], %1, 0x989680;\n\t"
        "@!P bra W_%=;\n\t}"
        :: "r"(mb), "r"(parity) : "memory");
}

__device__ __forceinline__ uint32_t pack2h(__half a, __half b) {
    __half2 p(a, b);
    return *reinterpret_cast<uint32_t*>(&p);
}
__device__ __forceinline__ uint32_t packf2(float2 v) {
    return pack2h(__float2half(v.x), __float2half(v.y));
}

// ============================ prep kernels =================================
__global__ void prep_qkv(const float* __restrict__ Wq, const float* __restrict__ Wk,
                         const float* __restrict__ Wv) {
    int idx = blockIdx.x * 256 + threadIdx.x;
    if (idx >= H * 3 * S * S) return;
    int h = idx / (3 * S * S);
    int mat = (idx >> 12) % 3;
    int s = (idx >> 6) & 63, t = idx & 63;
    const float* W = (mat == 0) ? Wq : ((mat == 1) ? Wk : Wv);
    float v = W[(h * S + s) * S + t];
    uint32_t off = swz128((uint32_t)(s * 128 + t * 2));
    *reinterpret_cast<__half*>(g_wqkv + (size_t)(h * 3 + mat) * 8192 + off) = __float2half(v);
}
__global__ void prep_wu(const float* __restrict__ Wu) {
    int idx = blockIdx.x * 256 + threadIdx.x;
    if (idx >= E * E) return;
    int k = idx >> 9, n = idx & 511;
    int kc = k >> 6, kk = k & 63, nh = n >> 8, nn = n & 255;
    size_t base = (size_t)(nh * 8 + kc) * 32768;
    uint32_t off = swz512((uint32_t)(kk * 512 + nn * 2));
    *reinterpret_cast<__half*>(g_wub + base + off) = __float2half(Wu[idx]);
}

// ============================ fused kernel =================================
// smem map (bytes), 112.06KB -> still 2 CTAs/SM (2 x 114752 + reserve <= 228KB):
//   sT  @ 0      : 8 tiles [64r x 64k] fp16 SW128 = 64KB
//   BUF @ 65536  : phase1 = W head-pair (48KB); phase2 = B ring 3 x 16KB
//   MB  @ 114688 : 6 mbarriers (3 full + 3 empty), 48B — IN BOUNDS now
constexpr uint32_t ST = 0, BUF = 65536;
constexpr uint32_t MB_FULL  = 114688;
constexpr uint32_t MB_EMPTY = 114688 + 24;
constexpr uint32_t SMEM_TOTAL = 114752;

__global__ __launch_bounds__(256, 2)
void fused_sparse_attn(const float* __restrict__ x,
                       const float* __restrict__ bq, const float* __restrict__ bk,
                       const float* __restrict__ bv,
                       const float* __restrict__ bu, float* __restrict__ out)
{
    extern __shared__ unsigned char smem[];
    const uint32_t sb = smem_u32(smem);
    const int tid = threadIdx.x, lane = tid & 31, wid = tid >> 5;
    const int row0 = blockIdx.x * TM;
    const float SC = 0.04419417382415922f;   // 1/sqrt(512)

    const int g  = lane >> 2;
    const int qd = lane & 3;
    const uint32_t hiSel = (uint32_t)((lane >> 4) << 4);

    // init phase-2 mbarriers up front (region untouched by phase 1)
    if (tid == 0) {
        #pragma unroll
        for (int b = 0; b < 3; ++b) {
            MBAR_INIT(sb + MB_FULL  + (uint32_t)b * 8, 256);
            MBAR_INIT(sb + MB_EMPTY + (uint32_t)b * 8, 256);
        }
    }

    // ===================== Phase 1: QKV + softmax -> sT ====================
    const int lh = wid >> 2;                  // local head in pair
    const int wm = wid & 3;                   // 16-row m position

    for (int hp = 0; hp < 4; ++hp) {
        // -- stage W head-pair (pre-swizzled, 48KB contiguous) --
        {
            const char* src = (const char*)g_wqkv + (size_t)hp * 49152;
            #pragma unroll
            for (int i = 0; i < 12; ++i) {
                uint32_t o = (uint32_t)(tid + i * 256) * 16;
                cp16(sb + BUF + o, src + o);
            }
            CP_COMMIT();
        }
        // -- A fragments straight from gmem (overlaps the cp.async W load) --
        uint32_t aF[4][4];
        {
            const float* xr0 = x + (size_t)(row0 + wm * 16 + g) * E + hp * 128 + lh * 64;
            const float* xr1 = xr0 + 8 * (size_t)E;
            #pragma unroll
            for (int ks = 0; ks < 4; ++ks) {
                int c = ks * 16 + qd * 2;
                aF[ks][0] = packf2(*reinterpret_cast<const float2*>(xr0 + c));
                aF[ks][1] = packf2(*reinterpret_cast<const float2*>(xr1 + c));
                aF[ks][2] = packf2(*reinterpret_cast<const float2*>(xr0 + c + 8));
                aF[ks][3] = packf2(*reinterpret_cast<const float2*>(xr1 + c + 8));
            }
        }
        CP_WAIT(0);
        __syncthreads();          // W(hp) visible to all warps

        const int h = hp * 2 + lh;
        const uint32_t wbase = sb + BUF + (uint32_t)lh * 24576;

        float aq[8][4], ak[8][4];
        #pragma unroll
        for (int nt = 0; nt < 8; ++nt)
            #pragma unroll
            for (int c = 0; c < 4; ++c) { aq[nt][c] = 0.f; ak[nt][c] = 0.f; }

        // pass A: q and k
        #pragma unroll
        for (int ks = 0; ks < 4; ++ks) {
            #pragma unroll
            for (int ntp = 0; ntp < 4; ++ntp) {
                uint32_t boff = swz128((uint32_t)(ks * 16 + (lane & 15)) * 128
                                       + (uint32_t)ntp * 32 + hiSel);
                uint32_t bQ[4], bK[4];
                ldsm_x4t(bQ, wbase + boff);
                ldsm_x4t(bK, wbase + 8192 + boff);
                mma16816(aq[2*ntp],   aF[ks], bQ[0], bQ[1]);
                mma16816(aq[2*ntp+1], aF[ks], bQ[2], bQ[3]);
                mma16816(ak[2*ntp],   aF[ks], bK[0], bK[1]);
                mma16816(ak[2*ntp+1], aF[ks], bK[2], bK[3]);
            }
        }
        // pass B: v
        float av[8][4];
        #pragma unroll
        for (int nt = 0; nt < 8; ++nt)
            #pragma unroll
            for (int c = 0; c < 4; ++c) av[nt][c] = 0.f;
        #pragma unroll
        for (int ks = 0; ks < 4; ++ks) {
            #pragma unroll
            for (int ntp = 0; ntp < 4; ++ntp) {
                uint32_t boff = swz128((uint32_t)(ks * 16 + (lane & 15)) * 128
                                       + (uint32_t)ntp * 32 + hiSel);
                uint32_t bV[4];
                ldsm_x4t(bV, wbase + 16384 + boff);
                mma16816(av[2*ntp],   aF[ks], bV[0], bV[1]);
                mma16816(av[2*ntp+1], aF[ks], bV[2], bV[3]);
            }
        }

        // -- softmax (quad-local), reuse aq<-e, av<-v+bias --
        const float* bqh = bq + h * S;
        const float* bkh = bk + h * S;
        const float* bvh = bv + h * S;
        float ssum0 = 0.f, ssum1 = 0.f;
        #pragma unroll
        for (int nt = 0; nt < 8; ++nt) {
            int col0 = nt * 8 + qd * 2;
            float2 b1 = *reinterpret_cast<const float2*>(bqh + col0);
            float2 b2 = *reinterpret_cast<const float2*>(bkh + col0);
            float2 b3 = *reinterpret_cast<const float2*>(bvh + col0);
            float e;
            e = __expf((aq[nt][0] + b1.x) * (ak[nt][0] + b2.x) * SC); aq[nt][0] = e; ssum0 += e;
            e = __expf((aq[nt][1] + b1.y) * (ak[nt][1] + b2.y) * SC); aq[nt][1] = e; ssum0 += e;
            e = __expf((aq[nt][2] + b1.x) * (ak[nt][2] + b2.x) * SC); aq[nt][2] = e; ssum1 += e;
            e = __expf((aq[nt][3] + b1.y) * (ak[nt][3] + b2.y) * SC); aq[nt][3] = e; ssum1 += e;
            av[nt][0] += b3.x; av[nt][1] += b3.y;
            av[nt][2] += b3.x; av[nt][3] += b3.y;
        }
        ssum0 += __shfl_xor_sync(0xffffffffu, ssum0, 1);
        ssum0 += __shfl_xor_sync(0xffffffffu, ssum0, 2);
        ssum1 += __shfl_xor_sync(0xffffffffu, ssum1, 1);
        ssum1 += __shfl_xor_sync(0xffffffffu, ssum1, 2);
        const float inv0 = 1.0f / ssum0, inv1 = 1.0f / ssum1;

        {
            int rt0 = wm * 16 + g;
            #pragma unroll
            for (int nt = 0; nt < 8; ++nt) {
                uint32_t cb = (uint32_t)((nt * 8 + qd * 2) * 2);
                uint32_t offBase = (uint32_t)h * 8192;
                float t0 = aq[nt][0] * inv0 * av[nt][0];
                float t1 = aq[nt][1] * inv0 * av[nt][1];
                float t2 = aq[nt][2] * inv1 * av[nt][2];
                float t3 = aq[nt][3] * inv1 * av[nt][3];
                *reinterpret_cast<uint32_t*>(smem + ST + offBase
                    + swz128((uint32_t)rt0 * 128 + cb)) =
                    pack2h(__float2half(t0), __float2half(t1));
                *reinterpret_cast<uint32_t*>(smem + ST + offBase
                    + swz128((uint32_t)(rt0 + 8) * 128 + cb)) =
                    pack2h(__float2half(t2), __float2half(t3));
            }
        }
        __syncthreads();   // BUF (W) safe to overwrite; sT coherent after last hp
    }
    // after final barrier: sT coherent, BUF free, mbarriers initialized & visible

    // ===================== Phase 2: out = t @ Wu_hi + bu ===================
    // warp = 64 rows x 32 cols (pn = wid): B read exactly once.
    // B ring: 3 x 16KB, mbarrier full/empty, lookahead 2 -> no block-wide BAR.
    const int pn = wid;

    auto load_sub = [&](int s, int buf) {
        int nh = s >> 4, kc = (s >> 1) & 7, half = s & 1;
        const char* src = (const char*)g_wub + (size_t)(nh * 8 + kc) * 32768
                        + (size_t)half * 16384;
        uint32_t d = sb + BUF + (uint32_t)buf * 16384;
        #pragma unroll
        for (int i = 0; i < 4; ++i) {
            uint32_t o = (uint32_t)(tid + i * 256) * 16;
            cp16(d + o, src + o);
        }
        cp_mbar_arrive_noinc(sb + MB_FULL + (uint32_t)buf * 8);
    };

    // prologue: fill the ring
    load_sub(0, 0);
    load_sub(1, 1);
    load_sub(2, 2);

    for (int nh = 0; nh < 2; ++nh) {
        float acc[16][4];   // [mf*4 + nf]
        #pragma unroll
        for (int nf = 0; nf < 16; ++nf)
            #pragma unroll
            for (int c = 0; c < 4; ++c) acc[nf][c] = 0.f;

        for (int s16 = 0; s16 < 16; ++s16) {
            const int s = nh * 16 + s16;
            const int b = s % 3;

            // prefetch step s+2 into buffer (s+2)%3 (last released at step s-1)
            if (s >= 1 && s + 2 < 32) {
                const int b2 = (s + 2) % 3;
                mbar_wait(sb + MB_EMPTY + (uint32_t)b2 * 8, (uint32_t)(((s - 1) / 3) & 1));
                load_sub(s + 2, b2);
            }

            // wait data for step s (phase index s/3)
            mbar_wait(sb + MB_FULL + (uint32_t)b * 8, (uint32_t)((s / 3) & 1));

            const int kc = s16 >> 1, half = s16 & 1;
            const uint32_t bb = sb + BUF + (uint32_t)b * 16384;
            const uint32_t tA = sb + ST + (uint32_t)kc * 8192;
            #pragma unroll
            for (int ksg = 0; ksg < 2; ++ksg) {
                uint32_t kOff = (uint32_t)(half * 64 + ksg * 32) + hiSel;
                uint32_t a[4][4];
                #pragma unroll
                for (int mf = 0; mf < 4; ++mf)
                    ldsm_x4(a[mf], tA + swz128((uint32_t)(mf * 16 + (lane & 15)) * 128 + kOff));
                #pragma unroll
                for (int ntp = 0; ntp < 2; ++ntp) {
                    uint32_t boff = swz512((uint32_t)(ksg * 16 + (lane & 15)) * 512
                                           + (uint32_t)(pn * 64 + ntp * 32) + hiSel);
                    uint32_t bfr[4];
                    ldsm_x4t(bfr, bb + boff);
                    #pragma unroll
                    for (int mf = 0; mf < 4; ++mf) {
                        mma16816(acc[mf * 4 + ntp * 2],     a[mf], bfr[0], bfr[1]);
                        mma16816(acc[mf * 4 + ntp * 2 + 1], a[mf], bfr[2], bfr[3]);
                    }
                }
            }

            // release buffer b (ldsm reads are complete in program order)
            mbar_arrive(sb + MB_EMPTY + (uint32_t)b * 8);
        }

        // epilogue for this N-half (warp-skewed, no sync needed)
        #pragma unroll
        for (int mf = 0; mf < 4; ++mf) {
            int r0 = row0 + mf * 16 + g;
            #pragma unroll
            for (int nf = 0; nf < 4; ++nf) {
                int col0 = nh * 256 + pn * 32 + nf * 8 + qd * 2;
                float2 bb2 = *reinterpret_cast<const float2*>(bu + col0);
                const float* a = acc[mf * 4 + nf];
                float2 o0 = make_float2(a[0] + bb2.x, a[1] + bb2.y);
                float2 o1 = make_float2(a[2] + bb2.x, a[3] + bb2.y);
                *reinterpret_cast<float2*>(out + (size_t)r0 * E + col0)       = o0;
                *reinterpret_cast<float2*>(out + (size_t)(r0 + 8) * E + col0) = o1;
            }
        }
    }
}

// ============================ launch =======================================
extern "C" void kernel_launch(void* const* d_in, const int* in_sizes, int n_in,
                              void* d_out, int out_size)
{
    const float* x  = (const float*)d_in[0];
    const float* Wq = (const float*)d_in[1];
    const float* bq = (const float*)d_in[2];
    const float* Wk = (const float*)d_in[3];
    const float* bk = (const float*)d_in[4];
    const float* Wv = (const float*)d_in[5];
    const float* bv = (const float*)d_in[6];
    const float* Wu = (const float*)d_in[7];
    const float* bu = (const float*)d_in[8];
    float* out = (float*)d_out;

    const int Nrows = in_sizes[0] / E;
    const int tiles = Nrows / TM;   // 2048

    cudaFuncSetAttribute(fused_sparse_attn,
                         cudaFuncAttributeMaxDynamicSharedMemorySize, SMEM_TOTAL);

    prep_qkv<<<(H * 3 * S * S + 255) / 256, 256>>>(Wq, Wk, Wv);
    prep_wu<<<(E * E + 255) / 256, 256>>>(Wu);
    fused_sparse_attn<<<tiles, 256, SMEM_TOTAL>>>(x, bq, bk, bv, bu, out);
}

// round 16
// speedup vs baseline: 1.2198x; 1.0511x over previous
#include <cuda_runtime.h>
#include <cuda_fp16.h>
#include <cstdint>

// ============================ problem constants ============================
constexpr int E = 512, H = 8, S = 64, TM = 64;

// ============================ device scratch (weights only) ================
// per head: {q_hi, k_hi, v_hi} 64x64 fp16 [s][t] SW128 tiles (8KB each) = 24KB/head
__device__ __align__(1024) unsigned char g_wqkv[H * 3 * 8192];
// Wu fragment image: [s(32)][pn(8)][j(4)][lane(32)][16B]  = 512KB
// j = ksg*2 + ntp ; 16B = regs r0..r3 (uint32 half2 each), exact mma B-frag image
__device__ __align__(1024) unsigned char g_wubf[32 * 8 * 4 * 32 * 16];

// ============================ helpers ======================================
__device__ __forceinline__ uint32_t smem_u32(const void* p) {
    uint32_t a;
    asm("{ .reg .u64 t; cvta.to.shared.u64 t, %1; cvt.u32.u64 %0, t; }" : "=r"(a) : "l"(p));
    return a;
}
__host__ __device__ __forceinline__ uint32_t swz128(uint32_t o) { return o ^ ((o >> 3) & 0x70); }

__device__ __forceinline__ void ldsm_x4(uint32_t (&r)[4], uint32_t a) {
    asm volatile("ldmatrix.sync.aligned.m8n8.x4.shared.b16 {%0,%1,%2,%3}, [%4];"
        : "=r"(r[0]), "=r"(r[1]), "=r"(r[2]), "=r"(r[3]) : "r"(a));
}
__device__ __forceinline__ void ldsm_x4t(uint32_t (&r)[4], uint32_t a) {
    asm volatile("ldmatrix.sync.aligned.m8n8.x4.trans.shared.b16 {%0,%1,%2,%3}, [%4];"
        : "=r"(r[0]), "=r"(r[1]), "=r"(r[2]), "=r"(r[3]) : "r"(a));
}
__device__ __forceinline__ void mma16816(float (&d)[4], const uint32_t (&a)[4],
                                         uint32_t b0, uint32_t b1) {
    asm volatile("mma.sync.aligned.m16n8k16.row.col.f32.f16.f16.f32 "
        "{%0,%1,%2,%3}, {%4,%5,%6,%7}, {%8,%9}, {%0,%1,%2,%3};"
        : "+f"(d[0]), "+f"(d[1]), "+f"(d[2]), "+f"(d[3])
        : "r"(a[0]), "r"(a[1]), "r"(a[2]), "r"(a[3]), "r"(b0), "r"(b1));
}
__device__ __forceinline__ void cp16(uint32_t dst, const void* src) {
    asm volatile("cp.async.cg.shared.global [%0], [%1], 16;" :: "r"(dst), "l"(src));
}
#define CP_COMMIT() asm volatile("cp.async.commit_group;" ::: "memory")
#define CP_WAIT(n)  asm volatile("cp.async.wait_group %0;" :: "n"(n) : "memory")

__device__ __forceinline__ uint32_t pack2h(__half a, __half b) {
    __half2 p(a, b);
    return *reinterpret_cast<uint32_t*>(&p);
}
__device__ __forceinline__ uint32_t packf2(float2 v) {
    return pack2h(__float2half(v.x), __float2half(v.y));
}

// ============================ prep kernels =================================
__global__ void prep_qkv(const float* __restrict__ Wq, const float* __restrict__ Wk,
                         const float* __restrict__ Wv) {
    int idx = blockIdx.x * 256 + threadIdx.x;
    if (idx >= H * 3 * S * S) return;
    int h = idx / (3 * S * S);
    int mat = (idx >> 12) % 3;
    int s = (idx >> 6) & 63, t = idx & 63;
    const float* W = (mat == 0) ? Wq : ((mat == 1) ? Wk : Wv);
    float v = W[(h * S + s) * S + t];
    uint32_t off = swz128((uint32_t)(s * 128 + t * 2));
    *reinterpret_cast<__half*>(g_wqkv + (size_t)(h * 3 + mat) * 8192 + off) = __float2half(v);
}
// Build the Wu fragment image. One thread per uint32 (half2):
// idx = (((s*8+pn)*4 + j)*32 + T)*4 + r
// k = kc*64 + half*32 + ksg*16 + 2*(T%4) + 8*(r&1)   (kc=s16>>1, half=s16&1, ksg=j>>1)
// n = nh*256 + pn*32 + ntp*16 + (T>>2) + 8*(r>>1)    (nh=s>>4, ntp=j&1)
__global__ void prep_wu(const float* __restrict__ Wu) {
    int idx = blockIdx.x * 256 + threadIdx.x;
    if (idx >= 131072) return;
    int r  = idx & 3;
    int T  = (idx >> 2) & 31;
    int j  = (idx >> 7) & 3;
    int pn = (idx >> 9) & 7;
    int s  = idx >> 12;
    int nh = s >> 4, s16 = s & 15;
    int kc = s16 >> 1, half = s16 & 1;
    int ksg = j >> 1, ntp = j & 1;
    int k = kc * 64 + half * 32 + ksg * 16 + 2 * (T & 3) + 8 * (r & 1);
    int n = nh * 256 + pn * 32 + ntp * 16 + (T >> 2) + 8 * (r >> 1);
    uint32_t v = pack2h(__float2half(Wu[k * E + n]), __float2half(Wu[(k + 1) * E + n]));
    reinterpret_cast<uint32_t*>(g_wubf)[idx] = v;
}

// ============================ fused kernel =================================
// smem map (bytes), 112KB -> 2 CTAs/SM:
//   sT  @ 0     : 8 tiles [64r x 64k] fp16 SW128 (head h = k-chunk h) = 64KB
//   BUF @ 65536 : phase1 W head-pair (48KB). Phase 2 uses NO smem beyond sT.
constexpr uint32_t ST = 0, BUF = 65536;
constexpr uint32_t SMEM_TOTAL = 114688;

__global__ __launch_bounds__(256, 2)
void fused_sparse_attn(const float* __restrict__ x,
                       const float* __restrict__ bq, const float* __restrict__ bk,
                       const float* __restrict__ bv,
                       const float* __restrict__ bu, float* __restrict__ out)
{
    extern __shared__ unsigned char smem[];
    const uint32_t sb = smem_u32(smem);
    const int tid = threadIdx.x, lane = tid & 31, wid = tid >> 5;
    const int row0 = blockIdx.x * TM;
    const float SC = 0.04419417382415922f;   // 1/sqrt(512)

    const int g  = lane >> 2;
    const int qd = lane & 3;
    const uint32_t hiSel = (uint32_t)((lane >> 4) << 4);

    // ===================== Phase 1: QKV + softmax -> sT ====================
    const int lh = wid >> 2;                  // local head in pair
    const int wm = wid & 3;                   // 16-row m position

    for (int hp = 0; hp < 4; ++hp) {
        // -- stage W head-pair (pre-swizzled, 48KB contiguous) --
        {
            const char* src = (const char*)g_wqkv + (size_t)hp * 49152;
            #pragma unroll
            for (int i = 0; i < 12; ++i) {
                uint32_t o = (uint32_t)(tid + i * 256) * 16;
                cp16(sb + BUF + o, src + o);
            }
            CP_COMMIT();
        }
        // -- A fragments straight from gmem (overlaps the cp.async W load) --
        uint32_t aF[4][4];
        {
            const float* xr0 = x + (size_t)(row0 + wm * 16 + g) * E + hp * 128 + lh * 64;
            const float* xr1 = xr0 + 8 * (size_t)E;
            #pragma unroll
            for (int ks = 0; ks < 4; ++ks) {
                int c = ks * 16 + qd * 2;
                aF[ks][0] = packf2(*reinterpret_cast<const float2*>(xr0 + c));
                aF[ks][1] = packf2(*reinterpret_cast<const float2*>(xr1 + c));
                aF[ks][2] = packf2(*reinterpret_cast<const float2*>(xr0 + c + 8));
                aF[ks][3] = packf2(*reinterpret_cast<const float2*>(xr1 + c + 8));
            }
        }
        CP_WAIT(0);
        __syncthreads();          // W(hp) visible to all warps

        const int h = hp * 2 + lh;
        const uint32_t wbase = sb + BUF + (uint32_t)lh * 24576;

        float aq[8][4], ak[8][4];
        #pragma unroll
        for (int nt = 0; nt < 8; ++nt)
            #pragma unroll
            for (int c = 0; c < 4; ++c) { aq[nt][c] = 0.f; ak[nt][c] = 0.f; }

        // pass A: q and k
        #pragma unroll
        for (int ks = 0; ks < 4; ++ks) {
            #pragma unroll
            for (int ntp = 0; ntp < 4; ++ntp) {
                uint32_t boff = swz128((uint32_t)(ks * 16 + (lane & 15)) * 128
                                       + (uint32_t)ntp * 32 + hiSel);
                uint32_t bQ[4], bK[4];
                ldsm_x4t(bQ, wbase + boff);
                ldsm_x4t(bK, wbase + 8192 + boff);
                mma16816(aq[2*ntp],   aF[ks], bQ[0], bQ[1]);
                mma16816(aq[2*ntp+1], aF[ks], bQ[2], bQ[3]);
                mma16816(ak[2*ntp],   aF[ks], bK[0], bK[1]);
                mma16816(ak[2*ntp+1], aF[ks], bK[2], bK[3]);
            }
        }
        // pass B: v
        float av[8][4];
        #pragma unroll
        for (int nt = 0; nt < 8; ++nt)
            #pragma unroll
            for (int c = 0; c < 4; ++c) av[nt][c] = 0.f;
        #pragma unroll
        for (int ks = 0; ks < 4; ++ks) {
            #pragma unroll
            for (int ntp = 0; ntp < 4; ++ntp) {
                uint32_t boff = swz128((uint32_t)(ks * 16 + (lane & 15)) * 128
                                       + (uint32_t)ntp * 32 + hiSel);
                uint32_t bV[4];
                ldsm_x4t(bV, wbase + 16384 + boff);
                mma16816(av[2*ntp],   aF[ks], bV[0], bV[1]);
                mma16816(av[2*ntp+1], aF[ks], bV[2], bV[3]);
            }
        }

        // -- softmax (quad-local), reuse aq<-e, av<-v+bias --
        const float* bqh = bq + h * S;
        const float* bkh = bk + h * S;
        const float* bvh = bv + h * S;
        float ssum0 = 0.f, ssum1 = 0.f;
        #pragma unroll
        for (int nt = 0; nt < 8; ++nt) {
            int col0 = nt * 8 + qd * 2;
            float2 b1 = *reinterpret_cast<const float2*>(bqh + col0);
            float2 b2 = *reinterpret_cast<const float2*>(bkh + col0);
            float2 b3 = *reinterpret_cast<const float2*>(bvh + col0);
            float e;
            e = __expf((aq[nt][0] + b1.x) * (ak[nt][0] + b2.x) * SC); aq[nt][0] = e; ssum0 += e;
            e = __expf((aq[nt][1] + b1.y) * (ak[nt][1] + b2.y) * SC); aq[nt][1] = e; ssum0 += e;
            e = __expf((aq[nt][2] + b1.x) * (ak[nt][2] + b2.x) * SC); aq[nt][2] = e; ssum1 += e;
            e = __expf((aq[nt][3] + b1.y) * (ak[nt][3] + b2.y) * SC); aq[nt][3] = e; ssum1 += e;
            av[nt][0] += b3.x; av[nt][1] += b3.y;
            av[nt][2] += b3.x; av[nt][3] += b3.y;
        }
        ssum0 += __shfl_xor_sync(0xffffffffu, ssum0, 1);
        ssum0 += __shfl_xor_sync(0xffffffffu, ssum0, 2);
        ssum1 += __shfl_xor_sync(0xffffffffu, ssum1, 1);
        ssum1 += __shfl_xor_sync(0xffffffffu, ssum1, 2);
        const float inv0 = 1.0f / ssum0, inv1 = 1.0f / ssum1;

        {
            int rt0 = wm * 16 + g;
            #pragma unroll
            for (int nt = 0; nt < 8; ++nt) {
                uint32_t cb = (uint32_t)((nt * 8 + qd * 2) * 2);
                uint32_t offBase = (uint32_t)h * 8192;
                float t0 = aq[nt][0] * inv0 * av[nt][0];
                float t1 = aq[nt][1] * inv0 * av[nt][1];
                float t2 = aq[nt][2] * inv1 * av[nt][2];
                float t3 = aq[nt][3] * inv1 * av[nt][3];
                *reinterpret_cast<uint32_t*>(smem + ST + offBase
                    + swz128((uint32_t)rt0 * 128 + cb)) =
                    pack2h(__float2half(t0), __float2half(t1));
                *reinterpret_cast<uint32_t*>(smem + ST + offBase
                    + swz128((uint32_t)(rt0 + 8) * 128 + cb)) =
                    pack2h(__float2half(t2), __float2half(t3));
            }
        }
        __syncthreads();   // BUF (W) safe to overwrite; sT coherent after last hp
    }
    // after the final barrier: sT coherent and read-only. Phase 2 is SYNC-FREE.

    // ===================== Phase 2: out = t @ Wu_hi + bu ===================
    // warp = 64 rows x 32 cols (pn = wid). B comes from the pre-packed fragment
    // image via coalesced LDG.128 straight to registers: NO smem staging, NO
    // barriers, NO cp.async. 1-step register lookahead hides L2 latency.
    const int pn = wid;

    // lane's 4 fragment chunks for step s start at:
    //   g_wubf + (((s*8+pn)*4 + 0)*32 + lane)*16 , stride 512B per chunk j
    const uint4* __restrict__ bimg = reinterpret_cast<const uint4*>(g_wubf);
    auto bidx = [&](int s, int j) -> size_t {
        return (((size_t)s * 8 + pn) * 4 + j) * 32 + lane;
    };

    uint4 Bc[4], Bn[4];
    #pragma unroll
    for (int j = 0; j < 4; ++j) Bc[j] = __ldg(&bimg[bidx(0, j)]);

    for (int nh = 0; nh < 2; ++nh) {
        float acc[16][4];   // [mf*4 + nf]
        #pragma unroll
        for (int nf = 0; nf < 16; ++nf)
            #pragma unroll
            for (int c = 0; c < 4; ++c) acc[nf][c] = 0.f;

        for (int s16 = 0; s16 < 16; ++s16) {
            const int s = nh * 16 + s16;
            // prefetch next step's B fragments (registers)
            if (s + 1 < 32) {
                #pragma unroll
                for (int j = 0; j < 4; ++j) Bn[j] = __ldg(&bimg[bidx(s + 1, j)]);
            }

            const int kc = s16 >> 1, half = s16 & 1;
            const uint32_t tA = sb + ST + (uint32_t)kc * 8192;
            #pragma unroll
            for (int ksg = 0; ksg < 2; ++ksg) {
                uint32_t kOff = (uint32_t)(half * 64 + ksg * 32) + hiSel;
                uint32_t a[4][4];
                #pragma unroll
                for (int mf = 0; mf < 4; ++mf)
                    ldsm_x4(a[mf], tA + swz128((uint32_t)(mf * 16 + (lane & 15)) * 128 + kOff));
                #pragma unroll
                for (int ntp = 0; ntp < 2; ++ntp) {
                    const uint4 B = Bc[ksg * 2 + ntp];
                    #pragma unroll
                    for (int mf = 0; mf < 4; ++mf) {
                        mma16816(acc[mf * 4 + ntp * 2],     a[mf], B.x, B.y);
                        mma16816(acc[mf * 4 + ntp * 2 + 1], a[mf], B.z, B.w);
                    }
                }
            }

            #pragma unroll
            for (int j = 0; j < 4; ++j) Bc[j] = Bn[j];
        }

        // epilogue for this N-half (warp-independent, no sync)
        #pragma unroll
        for (int mf = 0; mf < 4; ++mf) {
            int r0 = row0 + mf * 16 + g;
            #pragma unroll
            for (int nf = 0; nf < 4; ++nf) {
                int col0 = nh * 256 + pn * 32 + nf * 8 + qd * 2;
                float2 bb2 = *reinterpret_cast<const float2*>(bu + col0);
                const float* a = acc[mf * 4 + nf];
                float2 o0 = make_float2(a[0] + bb2.x, a[1] + bb2.y);
                float2 o1 = make_float2(a[2] + bb2.x, a[3] + bb2.y);
                *reinterpret_cast<float2*>(out + (size_t)r0 * E + col0)       = o0;
                *reinterpret_cast<float2*>(out + (size_t)(r0 + 8) * E + col0) = o1;
            }
        }
    }
}

// ============================ launch =======================================
extern "C" void kernel_launch(void* const* d_in, const int* in_sizes, int n_in,
                              void* d_out, int out_size)
{
    const float* x  = (const float*)d_in[0];
    const float* Wq = (const float*)d_in[1];
    const float* bq = (const float*)d_in[2];
    const float* Wk = (const float*)d_in[3];
    const float* bk = (const float*)d_in[4];
    const float* Wv = (const float*)d_in[5];
    const float* bv = (const float*)d_in[6];
    const float* Wu = (const float*)d_in[7];
    const float* bu = (const float*)d_in[8];
    float* out = (float*)d_out;

    const int Nrows = in_sizes[0] / E;
    const int tiles = Nrows / TM;   // 2048

    cudaFuncSetAttribute(fused_sparse_attn,
                         cudaFuncAttributeMaxDynamicSharedMemorySize, SMEM_TOTAL);

    prep_qkv<<<(H * 3 * S * S + 255) / 256, 256>>>(Wq, Wk, Wv);
    prep_wu<<<(131072 + 255) / 256, 256>>>(Wu);
    fused_sparse_attn<<<tiles, 256, SMEM_TOTAL>>>(x, bq, bk, bv, bu, out);
}

// round 17
// speedup vs baseline: 1.3494x; 1.1063x over previous
#include <cuda_runtime.h>
#include <cuda_fp16.h>
#include <cstdint>

// ============================ problem constants ============================
constexpr int E = 512, H = 8, S = 64, TM = 64;

// ============================ device scratch (weights only) ================
// Wq/Wk/Wv fragment image: [h(8)][mat(3)][ks(4)][ntp(4)][lane(32)][16B] = 192KB
__device__ __align__(1024) unsigned char g_wqkvf[8 * 3 * 4 * 4 * 32 * 16];
// Wu fragment image: [s(32)][pn(8)][j(4)][lane(32)][16B] = 512KB
__device__ __align__(1024) unsigned char g_wubf[32 * 8 * 4 * 32 * 16];

// ============================ helpers ======================================
__device__ __forceinline__ uint32_t smem_u32(const void* p) {
    uint32_t a;
    asm("{ .reg .u64 t; cvta.to.shared.u64 t, %1; cvt.u32.u64 %0, t; }" : "=r"(a) : "l"(p));
    return a;
}
__host__ __device__ __forceinline__ uint32_t swz128(uint32_t o) { return o ^ ((o >> 3) & 0x70); }

__device__ __forceinline__ void ldsm_x4(uint32_t (&r)[4], uint32_t a) {
    asm volatile("ldmatrix.sync.aligned.m8n8.x4.shared.b16 {%0,%1,%2,%3}, [%4];"
        : "=r"(r[0]), "=r"(r[1]), "=r"(r[2]), "=r"(r[3]) : "r"(a));
}
__device__ __forceinline__ void mma16816(float (&d)[4], const uint32_t (&a)[4],
                                         uint32_t b0, uint32_t b1) {
    asm volatile("mma.sync.aligned.m16n8k16.row.col.f32.f16.f16.f32 "
        "{%0,%1,%2,%3}, {%4,%5,%6,%7}, {%8,%9}, {%0,%1,%2,%3};"
        : "+f"(d[0]), "+f"(d[1]), "+f"(d[2]), "+f"(d[3])
        : "r"(a[0]), "r"(a[1]), "r"(a[2]), "r"(a[3]), "r"(b0), "r"(b1));
}

__device__ __forceinline__ uint32_t pack2h(__half a, __half b) {
    __half2 p(a, b);
    return *reinterpret_cast<uint32_t*>(&p);
}
__device__ __forceinline__ uint32_t packf2(float2 v) {
    return pack2h(__float2half(v.x), __float2half(v.y));
}

// ============================ prep kernels =================================
// W fragment image: idx over uint32s.
// idx = ((((h*3+mat)*4+ks)*4+ntp)*32+T)*4 + r
// k = ks*16 + 2*(T&3) + 8*(r&1) ; n = ntp*16 + (T>>2) + 8*(r>>1)
// value = pack(W[h][k][n], W[h][k+1][n])  (W row-major [h][s][t], k over s, n over t)
__global__ void prep_qkvf(const float* __restrict__ Wq, const float* __restrict__ Wk,
                          const float* __restrict__ Wv) {
    int idx = blockIdx.x * 256 + threadIdx.x;
    if (idx >= 8 * 3 * 4 * 4 * 32 * 4) return;
    int r   = idx & 3;
    int T   = (idx >> 2) & 31;
    int ntp = (idx >> 7) & 3;
    int ks  = (idx >> 9) & 3;
    int mat = (idx >> 11) % 3;
    int h   = idx / (3 * 4 * 4 * 32 * 4);
    const float* W = (mat == 0) ? Wq : ((mat == 1) ? Wk : Wv);
    int k = ks * 16 + 2 * (T & 3) + 8 * (r & 1);
    int n = ntp * 16 + (T >> 2) + 8 * (r >> 1);
    uint32_t v = pack2h(__float2half(W[(h * S + k) * S + n]),
                        __float2half(W[(h * S + k + 1) * S + n]));
    reinterpret_cast<uint32_t*>(g_wqkvf)[idx] = v;
}
// Wu fragment image (verified in R16):
// idx = (((s*8+pn)*4 + j)*32 + T)*4 + r
__global__ void prep_wu(const float* __restrict__ Wu) {
    int idx = blockIdx.x * 256 + threadIdx.x;
    if (idx >= 131072) return;
    int r  = idx & 3;
    int T  = (idx >> 2) & 31;
    int j  = (idx >> 7) & 3;
    int pn = (idx >> 9) & 7;
    int s  = idx >> 12;
    int nh = s >> 4, s16 = s & 15;
    int kc = s16 >> 1, half = s16 & 1;
    int ksg = j >> 1, ntp = j & 1;
    int k = kc * 64 + half * 32 + ksg * 16 + 2 * (T & 3) + 8 * (r & 1);
    int n = nh * 256 + pn * 32 + ntp * 16 + (T >> 2) + 8 * (r >> 1);
    uint32_t v = pack2h(__float2half(Wu[k * E + n]), __float2half(Wu[(k + 1) * E + n]));
    reinterpret_cast<uint32_t*>(g_wubf)[idx] = v;
}

// ============================ fused kernel =================================
// smem: sT only — 8 tiles [64r x 64k] fp16 SW128 (head h = k-chunk h) = 64KB.
// ONE __syncthreads in the whole kernel (phase boundary).
constexpr uint32_t ST = 0;
constexpr uint32_t SMEM_TOTAL = 65536;

__global__ __launch_bounds__(256, 2)
void fused_sparse_attn(const float* __restrict__ x,
                       const float* __restrict__ bq, const float* __restrict__ bk,
                       const float* __restrict__ bv,
                       const float* __restrict__ bu, float* __restrict__ out)
{
    extern __shared__ unsigned char smem[];
    const uint32_t sb = smem_u32(smem);
    const int tid = threadIdx.x, lane = tid & 31, wid = tid >> 5;
    const int row0 = blockIdx.x * TM;
    const float SC = 0.04419417382415922f;   // 1/sqrt(512)

    const int g  = lane >> 2;
    const int qd = lane & 3;
    const uint32_t hiSel = (uint32_t)((lane >> 4) << 4);

    // ===================== Phase 1: QKV + softmax -> sT ====================
    // warp (lh, wm): head hp*2+lh, rows wm*16..+15. Fully warp-independent:
    // x and W fragments come straight from gmem; sT rows are warp-private.
    const int lh = wid >> 2;
    const int wm = wid & 3;
    const uint4* __restrict__ wimg = reinterpret_cast<const uint4*>(g_wqkvf);

    for (int hp = 0; hp < 4; ++hp) {
        const int h = hp * 2 + lh;

        // -- A fragments straight from gmem --
        uint32_t aF[4][4];
        {
            const float* xr0 = x + (size_t)(row0 + wm * 16 + g) * E + hp * 128 + lh * 64;
            const float* xr1 = xr0 + 8 * (size_t)E;
            #pragma unroll
            for (int ks = 0; ks < 4; ++ks) {
                int c = ks * 16 + qd * 2;
                aF[ks][0] = packf2(*reinterpret_cast<const float2*>(xr0 + c));
                aF[ks][1] = packf2(*reinterpret_cast<const float2*>(xr1 + c));
                aF[ks][2] = packf2(*reinterpret_cast<const float2*>(xr0 + c + 8));
                aF[ks][3] = packf2(*reinterpret_cast<const float2*>(xr1 + c + 8));
            }
        }

        float aq[8][4], ak[8][4], av[8][4];
        #pragma unroll
        for (int nt = 0; nt < 8; ++nt)
            #pragma unroll
            for (int c = 0; c < 4; ++c) { aq[nt][c] = 0.f; ak[nt][c] = 0.f; av[nt][c] = 0.f; }

        // per-(ks,ntp): W fragments from image (coalesced 512B per fragment,
        // L1-shared across the 4 m-warps of this head)
        const size_t hb = (size_t)h * 3 * 512;   // in uint4: h*3 mats * (4*4*32)
        #pragma unroll
        for (int ks = 0; ks < 4; ++ks) {
            #pragma unroll
            for (int ntp = 0; ntp < 4; ++ntp) {
                size_t fo = (size_t)(ks * 4 + ntp) * 32 + lane;
                uint4 BQ = __ldg(&wimg[hb + fo]);
                uint4 BK = __ldg(&wimg[hb + 512 + fo]);
                uint4 BV = __ldg(&wimg[hb + 1024 + fo]);
                mma16816(aq[2*ntp],   aF[ks], BQ.x, BQ.y);
                mma16816(aq[2*ntp+1], aF[ks], BQ.z, BQ.w);
                mma16816(ak[2*ntp],   aF[ks], BK.x, BK.y);
                mma16816(ak[2*ntp+1], aF[ks], BK.z, BK.w);
                mma16816(av[2*ntp],   aF[ks], BV.x, BV.y);
                mma16816(av[2*ntp+1], aF[ks], BV.z, BV.w);
            }
        }

        // -- softmax (quad-local), reuse aq<-e, av<-v+bias --
        const float* bqh = bq + h * S;
        const float* bkh = bk + h * S;
        const float* bvh = bv + h * S;
        float ssum0 = 0.f, ssum1 = 0.f;
        #pragma unroll
        for (int nt = 0; nt < 8; ++nt) {
            int col0 = nt * 8 + qd * 2;
            float2 b1 = *reinterpret_cast<const float2*>(bqh + col0);
            float2 b2 = *reinterpret_cast<const float2*>(bkh + col0);
            float2 b3 = *reinterpret_cast<const float2*>(bvh + col0);
            float e;
            e = __expf((aq[nt][0] + b1.x) * (ak[nt][0] + b2.x) * SC); aq[nt][0] = e; ssum0 += e;
            e = __expf((aq[nt][1] + b1.y) * (ak[nt][1] + b2.y) * SC); aq[nt][1] = e; ssum0 += e;
            e = __expf((aq[nt][2] + b1.x) * (ak[nt][2] + b2.x) * SC); aq[nt][2] = e; ssum1 += e;
            e = __expf((aq[nt][3] + b1.y) * (ak[nt][3] + b2.y) * SC); aq[nt][3] = e; ssum1 += e;
            av[nt][0] += b3.x; av[nt][1] += b3.y;
            av[nt][2] += b3.x; av[nt][3] += b3.y;
        }
        ssum0 += __shfl_xor_sync(0xffffffffu, ssum0, 1);
        ssum0 += __shfl_xor_sync(0xffffffffu, ssum0, 2);
        ssum1 += __shfl_xor_sync(0xffffffffu, ssum1, 1);
        ssum1 += __shfl_xor_sync(0xffffffffu, ssum1, 2);
        const float inv0 = 1.0f / ssum0, inv1 = 1.0f / ssum1;

        {
            int rt0 = wm * 16 + g;
            #pragma unroll
            for (int nt = 0; nt < 8; ++nt) {
                uint32_t cb = (uint32_t)((nt * 8 + qd * 2) * 2);
                uint32_t offBase = (uint32_t)h * 8192;
                float t0 = aq[nt][0] * inv0 * av[nt][0];
                float t1 = aq[nt][1] * inv0 * av[nt][1];
                float t2 = aq[nt][2] * inv1 * av[nt][2];
                float t3 = aq[nt][3] * inv1 * av[nt][3];
                *reinterpret_cast<uint32_t*>(smem + ST + offBase
                    + swz128((uint32_t)rt0 * 128 + cb)) =
                    pack2h(__float2half(t0), __float2half(t1));
                *reinterpret_cast<uint32_t*>(smem + ST + offBase
                    + swz128((uint32_t)(rt0 + 8) * 128 + cb)) =
                    pack2h(__float2half(t2), __float2half(t3));
            }
        }
        // no barrier: next hp touches only gmem + this warp's private sT rows
    }
    __syncthreads();   // the ONLY block-wide barrier: sT coherent for phase 2

    // ===================== Phase 2: out = t @ Wu_hi + bu ===================
    // warp = 64 rows x 32 cols (pn = wid). B from gmem fragment image via
    // coalesced LDG.128; 1-step register lookahead. No smem writes, no sync.
    const int pn = wid;
    const uint4* __restrict__ bimg = reinterpret_cast<const uint4*>(g_wubf);
    auto bidx = [&](int s, int j) -> size_t {
        return (((size_t)s * 8 + pn) * 4 + j) * 32 + lane;
    };

    uint4 Bc[4], Bn[4];
    #pragma unroll
    for (int j = 0; j < 4; ++j) Bc[j] = __ldg(&bimg[bidx(0, j)]);

    for (int nh = 0; nh < 2; ++nh) {
        float acc[16][4];   // [mf*4 + nf]
        #pragma unroll
        for (int nf = 0; nf < 16; ++nf)
            #pragma unroll
            for (int c = 0; c < 4; ++c) acc[nf][c] = 0.f;

        for (int s16 = 0; s16 < 16; ++s16) {
            const int s = nh * 16 + s16;
            if (s + 1 < 32) {
                #pragma unroll
                for (int j = 0; j < 4; ++j) Bn[j] = __ldg(&bimg[bidx(s + 1, j)]);
            }

            const int kc = s16 >> 1, half = s16 & 1;
            const uint32_t tA = sb + ST + (uint32_t)kc * 8192;
            #pragma unroll
            for (int ksg = 0; ksg < 2; ++ksg) {
                uint32_t kOff = (uint32_t)(half * 64 + ksg * 32) + hiSel;
                uint32_t a[4][4];
                #pragma unroll
                for (int mf = 0; mf < 4; ++mf)
                    ldsm_x4(a[mf], tA + swz128((uint32_t)(mf * 16 + (lane & 15)) * 128 + kOff));
                #pragma unroll
                for (int ntp = 0; ntp < 2; ++ntp) {
                    const uint4 B = Bc[ksg * 2 + ntp];
                    #pragma unroll
                    for (int mf = 0; mf < 4; ++mf) {
                        mma16816(acc[mf * 4 + ntp * 2],     a[mf], B.x, B.y);
                        mma16816(acc[mf * 4 + ntp * 2 + 1], a[mf], B.z, B.w);
                    }
                }
            }

            #pragma unroll
            for (int j = 0; j < 4; ++j) Bc[j] = Bn[j];
        }

        // epilogue for this N-half (warp-independent)
        #pragma unroll
        for (int mf = 0; mf < 4; ++mf) {
            int r0 = row0 + mf * 16 + g;
            #pragma unroll
            for (int nf = 0; nf < 4; ++nf) {
                int col0 = nh * 256 + pn * 32 + nf * 8 + qd * 2;
                float2 bb2 = *reinterpret_cast<const float2*>(bu + col0);
                const float* a = acc[mf * 4 + nf];
                float2 o0 = make_float2(a[0] + bb2.x, a[1] + bb2.y);
                float2 o1 = make_float2(a[2] + bb2.x, a[3] + bb2.y);
                *reinterpret_cast<float2*>(out + (size_t)r0 * E + col0)       = o0;
                *reinterpret_cast<float2*>(out + (size_t)(r0 + 8) * E + col0) = o1;
            }
        }
    }
}

// ============================ launch =======================================
extern "C" void kernel_launch(void* const* d_in, const int* in_sizes, int n_in,
                              void* d_out, int out_size)
{
    const float* x  = (const float*)d_in[0];
    const float* Wq = (const float*)d_in[1];
    const float* bq = (const float*)d_in[2];
    const float* Wk = (const float*)d_in[3];
    const float* bk = (const float*)d_in[4];
    const float* Wv = (const float*)d_in[5];
    const float* bv = (const float*)d_in[6];
    const float* Wu = (const float*)d_in[7];
    const float* bu = (const float*)d_in[8];
    float* out = (float*)d_out;

    const int Nrows = in_sizes[0] / E;
    const int tiles = Nrows / TM;   // 2048

    cudaFuncSetAttribute(fused_sparse_attn,
                         cudaFuncAttributeMaxDynamicSharedMemorySize, SMEM_TOTAL);

    prep_qkvf<<<(8 * 3 * 4 * 4 * 32 * 4 + 255) / 256, 256>>>(Wq, Wk, Wv);
    prep_wu<<<(131072 + 255) / 256, 256>>>(Wu);
    fused_sparse_attn<<<tiles, 256, SMEM_TOTAL>>>(x, bq, bk, bv, bu, out);
}